// round 7
// baseline (speedup 1.0000x reference)
#include <cuda_runtime.h>
#include <math.h>

#define HID 256
#define QN 64
#define LQ 20
#define DN 24
#define LD 50
#define QROWS (QN*LQ)   // 1280
#define DROWS (DN*LD)   // 1200

typedef unsigned long long u64;

__device__ __forceinline__ u64 ffma2(u64 a, u64 b, u64 c) {
    u64 d; asm("fma.rn.f32x2 %0, %1, %2, %3;" : "=l"(d) : "l"(a), "l"(b), "l"(c)); return d;
}
__device__ __forceinline__ float hsum2(u64 s) {
    float lo, hi; asm("mov.b64 {%0, %1}, %2;" : "=f"(lo), "=f"(hi) : "l"(s)); return lo + hi;
}
__device__ __forceinline__ void unpack2(u64 s, float& lo, float& hi) {
    asm("mov.b64 {%0, %1}, %2;" : "=f"(lo), "=f"(hi) : "l"(s));
}
__device__ __forceinline__ u64 dupf(float v) {
    u64 d; asm("mov.b64 %0, {%1, %1};" : "=l"(d) : "f"(v)); return d;
}
__device__ __forceinline__ float dot4(float4 a, float4 b, float s) {
    s = fmaf(a.x, b.x, s); s = fmaf(a.y, b.y, s);
    s = fmaf(a.z, b.z, s); s = fmaf(a.w, b.w, s);
    return s;
}
__device__ __forceinline__ unsigned s2u(const void* p) {
    unsigned a;
    asm("{ .reg .u64 t; cvta.to.shared.u64 t, %1; cvt.u32.u64 %0, t; }" : "=r"(a) : "l"(p));
    return a;
}
__device__ __forceinline__ void st_peer(unsigned addr, unsigned rank, float v) {
    unsigned pa;
    asm("mapa.shared::cluster.u32 %0, %1, %2;" : "=r"(pa) : "r"(addr), "r"(rank));
    asm volatile("st.shared::cluster.f32 [%0], %1;" :: "r"(pa), "f"(v));
}
#define CLUSTER_ARRIVE() asm volatile("barrier.cluster.arrive.aligned;" ::: "memory")
#define CLUSTER_WAIT()   asm volatile("barrier.cluster.wait.aligned;" ::: "memory")

// ---------------- scratch ----------------------------------------------------
__device__ __align__(16) float g_giq[QROWS*768];
__device__ __align__(16) float g_gic[DROWS*768];
__device__ __align__(16) float g_gia[DROWS*768];
__device__ __align__(16) float g_hq[QN*HID];
__device__ __align__(16) float g_hc[DN*HID];
__device__ __align__(16) float g_ha[DN*HID];
__device__ __align__(16) float g_cfin[DN*HID];
__device__ __align__(16) float g_qpn[QN*HID];

// ---------------- K1: gi = emb[tok] @ W^T + b, gather fused, f32x2 -----------
#define GBM 128
#define GBN 192
#define GBK 32
#define ASD 132
#define BSD 196

__global__ void __launch_bounds__(256) gi_gemm_k(
    const int* __restrict__ qt, const int* __restrict__ pt, const int* __restrict__ nt,
    const float* __restrict__ temb, const float* __restrict__ demb,
    const float* __restrict__ tW, const float* __restrict__ tb,
    const float* __restrict__ cW, const float* __restrict__ cb,
    const float* __restrict__ aW, const float* __restrict__ ab) {
    __shared__ float As[GBK*ASD];
    __shared__ float Bs[GBK*BSD];
    __shared__ int toks[GBM];

    int bid = blockIdx.x;
    int tid = threadIdx.x;
    int seg = bid / 40;          // 0=query, 1=doc-c, 2=doc-a
    int rem = bid - seg*40;
    int mtl = rem >> 2, ntl = rem & 3;
    int m0 = mtl*GBM, n0 = ntl*GBN;

    const float* W; const float* bias; float* C; const float* emb; int M;
    if (seg == 0)      { W=tW; bias=tb; C=g_giq; emb=temb; M=QROWS; }
    else if (seg == 1) { W=cW; bias=cb; C=g_gic; emb=demb; M=DROWS; }
    else               { W=aW; bias=ab; C=g_gia; emb=demb; M=DROWS; }

    if (tid < GBM) {
        int m = m0 + tid;
        int tk = 0;
        if (m < M) {
            if (seg == 0) tk = qt[m];
            else tk = (m < 600) ? pt[m] : nt[m-600];
        }
        toks[tid] = tk;
    }
    __syncthreads();

    int tx = tid & 15, ty = tid >> 4;
    u64 acc2[4][12];
    #pragma unroll
    for (int p = 0; p < 4; p++)
        #pragma unroll
        for (int j = 0; j < 12; j++) acc2[p][j] = 0ull;

    for (int k0 = 0; k0 < HID; k0 += GBK) {
        #pragma unroll
        for (int q = 0; q < 4; q++) {
            int idx = q*256 + tid;
            int kq = idx >> 7, m = idx & 127;
            float4 v = make_float4(0.f,0.f,0.f,0.f);
            if (m0 + m < M) v = *(const float4*)(emb + (size_t)toks[m]*HID + k0 + kq*4);
            As[(kq*4+0)*ASD + m] = v.x; As[(kq*4+1)*ASD + m] = v.y;
            As[(kq*4+2)*ASD + m] = v.z; As[(kq*4+3)*ASD + m] = v.w;
        }
        #pragma unroll
        for (int q = 0; q < 6; q++) {
            int idx = q*256 + tid;
            int kq = idx / 192, n = idx - kq*192;
            float4 v = *(const float4*)(W + (size_t)(n0+n)*HID + k0 + kq*4);
            Bs[(kq*4+0)*BSD + n] = v.x; Bs[(kq*4+1)*BSD + n] = v.y;
            Bs[(kq*4+2)*BSD + n] = v.z; Bs[(kq*4+3)*BSD + n] = v.w;
        }
        __syncthreads();
        #pragma unroll 8
        for (int k = 0; k < GBK; k++) {
            ulonglong2 A01 = *(const ulonglong2*)(As + k*ASD + ty*8);
            ulonglong2 A23 = *(const ulonglong2*)(As + k*ASD + ty*8 + 4);
            u64 a2[4] = {A01.x, A01.y, A23.x, A23.y};
            float4 b0 = *(const float4*)(Bs + k*BSD + tx*4);
            float4 b1 = *(const float4*)(Bs + k*BSD + 64 + tx*4);
            float4 b2 = *(const float4*)(Bs + k*BSD + 128 + tx*4);
            u64 bb[12];
            bb[0]=dupf(b0.x); bb[1]=dupf(b0.y); bb[2]=dupf(b0.z); bb[3]=dupf(b0.w);
            bb[4]=dupf(b1.x); bb[5]=dupf(b1.y); bb[6]=dupf(b1.z); bb[7]=dupf(b1.w);
            bb[8]=dupf(b2.x); bb[9]=dupf(b2.y); bb[10]=dupf(b2.z); bb[11]=dupf(b2.w);
            #pragma unroll
            for (int p = 0; p < 4; p++)
                #pragma unroll
                for (int j = 0; j < 12; j++)
                    acc2[p][j] = ffma2(a2[p], bb[j], acc2[p][j]);
        }
        __syncthreads();
    }

    float4 bv[3];
    #pragma unroll
    for (int g = 0; g < 3; g++)
        bv[g] = *(const float4*)(bias + n0 + g*64 + tx*4);
    #pragma unroll
    for (int p = 0; p < 4; p++) {
        float vlo[12], vhi[12];
        #pragma unroll
        for (int j = 0; j < 12; j++) unpack2(acc2[p][j], vlo[j], vhi[j]);
        #pragma unroll
        for (int e = 0; e < 2; e++) {
            int m = m0 + ty*8 + p*2 + e;
            if (m >= M) continue;
            const float* vv = e ? vhi : vlo;
            #pragma unroll
            for (int g = 0; g < 3; g++) {
                float4 o;
                o.x = vv[g*4+0] + (&bv[g].x)[0];
                o.y = vv[g*4+1] + (&bv[g].x)[1];
                o.z = vv[g*4+2] + (&bv[g].x)[2];
                o.w = vv[g*4+3] + (&bv[g].x)[3];
                *(float4*)(C + (size_t)m*768 + n0 + g*64 + tx*4) = o;
            }
        }
    }
}

// ---------------- K2: GRU scans, clusters of 16, DSMEM h exchange ------------
// doc CTAs 0..95:  cluster bg=bid/16 (4 docs, both chains), rank=bid%16 -> c0 span 16
// qry CTAs 96..127: clusters 6,7 each hold TWO 8-CTA groups (16 queries, span 32)
#define HBUF (16*256)

__global__ void __launch_bounds__(512) scan_k(
    const float* __restrict__ tWhh, const float* __restrict__ tbhh,
    const float* __restrict__ cWhh, const float* __restrict__ cbhh,
    const float* __restrict__ aWhh, const float* __restrict__ abhh) {
    __shared__ float h_s[2][HBUF];
    __shared__ float parts[96*17];

    int bid = blockIdx.x, tid = threadIdx.x;
    bool isQ = (bid >= 96);
    int lane = tid & 31;
    int r = lane & 7, ks = lane >> 3;
    int row = (tid >> 5)*8 + r;
    bool act = tid < 384;

    int bg, c0, T, PB;
    if (!isQ) { bg = bid >> 4; c0 = (bid & 15) << 4; T = LD; PB = 5; }
    else { int qg = bid - 96; bg = qg >> 3; c0 = (qg & 7) << 5; T = LQ; PB = 17; }

    // ---- W slice into registers (rotated chunk order for conflict-free h LDS)
    u64 wreg[32];
    int hrow0 = 0;
    if (act) {
        const float* Wp; int grow;
        if (!isQ) {
            int chain = row / 48, rr = row - (row/48)*48;
            grow = (rr >> 4)*256 + c0 + (rr & 15);
            Wp = chain ? aWhh : cWhh;
            hrow0 = chain * 4;
        } else {
            grow = (row >> 5)*256 + c0 + (row & 31);
            Wp = tWhh;
        }
        const float* base = Wp + (size_t)grow*HID + ks*64;
        #pragma unroll
        for (int i = 0; i < 8; i++) {
            int ch = (i + ks) & 7;
            ulonglong2 p0 = *(const ulonglong2*)(base + ch*8);
            ulonglong2 p1 = *(const ulonglong2*)(base + ch*8 + 4);
            wreg[i*4+0]=p0.x; wreg[i*4+1]=p0.y; wreg[i*4+2]=p1.x; wreg[i*4+3]=p1.y;
        }
    }

    // ---- phase-2 setup --------------------------------------------------------
    bool oact; int prI=0, pzI=0, pnI=0, hpDst=0, hoff=0, cc=0;
    float br=0.f, bz=0.f, bn=0.f;
    const float* giBase = nullptr;
    float* hgfin = nullptr;
    int rkb = 0, nrk = 16;
    if (!isQ) {
        oact = (tid < 128);
        if (oact) {
            int chain = tid >> 6, b = (tid >> 4) & 3, cl = tid & 15;
            cc = c0 + cl;
            prI = (chain*48 + cl)*PB + b; pzI = prI + 16*PB; pnI = prI + 32*PB;
            hpDst = (chain*4 + b)*256 + cc;
            const float* bh = chain ? abhh : cbhh;
            br = bh[cc]; bz = bh[256+cc]; bn = bh[512+cc];
            giBase = (chain ? g_gia : g_gic) + (size_t)(bg*4 + b)*LD*768;
            hoff = (bg*4 + b)*256 + cc;
            hgfin = chain ? g_ha : g_hc;
        }
    } else {
        oact = true;
        int b = tid >> 5, cl = tid & 31;
        cc = c0 + cl;
        prI = cl*PB + b; pzI = (32+cl)*PB + b; pnI = (64+cl)*PB + b;
        hpDst = b*256 + cc;
        br = tbhh[cc]; bz = tbhh[256+cc]; bn = tbhh[512+cc];
        giBase = g_giq + (size_t)(bg*16 + b)*LQ*768;
        hoff = (bg*16 + b)*256 + cc;
        hgfin = g_hq;
        rkb = (bg & 1) * 8; nrk = 8;     // peers = my 8-CTA group within the 16-CTA cluster
    }
    unsigned dst0 = oact ? s2u(&h_s[0][hpDst]) : 0u;

    // ---- zero h buffer 0 (h0 = 0); buffer 1 fully written at t=0 --------------
    #pragma unroll
    for (int i = 0; i < 2; i++)
        ((float4*)h_s[0])[tid + i*512] = make_float4(0.f,0.f,0.f,0.f);
    __syncthreads();

    for (int t = 0; t < T; t++) {
        int cur = t & 1, nb = cur ^ 1;
        float xr=0.f, xz=0.f, xn=0.f;
        if (oact) {
            const float* gp = giBase + (size_t)t*768;
            xr = __ldcg(gp + cc); xz = __ldcg(gp + 256 + cc); xn = __ldcg(gp + 512 + cc);
        }
        // phase 1: gh partials, W in regs, h from smem
        if (act) {
            const float* hb = h_s[cur];
            if (!isQ) {
                u64 acc[4];
                #pragma unroll
                for (int b = 0; b < 4; b++) acc[b] = 0ull;
                #pragma unroll
                for (int i = 0; i < 8; i++) {
                    int off = ((i + ks) & 7) * 8 + ks*64;
                    #pragma unroll
                    for (int b = 0; b < 4; b++) {
                        const float* hp = hb + (hrow0 + b)*256 + off;
                        ulonglong2 h0 = *(const ulonglong2*)hp;
                        ulonglong2 h1 = *(const ulonglong2*)(hp + 4);
                        acc[b] = ffma2(h0.x, wreg[i*4+0], acc[b]);
                        acc[b] = ffma2(h0.y, wreg[i*4+1], acc[b]);
                        acc[b] = ffma2(h1.x, wreg[i*4+2], acc[b]);
                        acc[b] = ffma2(h1.y, wreg[i*4+3], acc[b]);
                    }
                }
                #pragma unroll
                for (int b = 0; b < 4; b++) {
                    float s = hsum2(acc[b]);
                    s += __shfl_xor_sync(0xffffffffu, s, 8);
                    s += __shfl_xor_sync(0xffffffffu, s, 16);
                    if (ks == 0) parts[row*5 + b] = s;
                }
            } else {
                #pragma unroll
                for (int half = 0; half < 2; half++) {
                    u64 acc[8];
                    #pragma unroll
                    for (int b = 0; b < 8; b++) acc[b] = 0ull;
                    #pragma unroll
                    for (int i = 0; i < 8; i++) {
                        int off = ((i + ks) & 7) * 8 + ks*64;
                        #pragma unroll
                        for (int b = 0; b < 8; b++) {
                            const float* hp = hb + (half*8 + b)*256 + off;
                            ulonglong2 h0 = *(const ulonglong2*)hp;
                            ulonglong2 h1 = *(const ulonglong2*)(hp + 4);
                            acc[b] = ffma2(h0.x, wreg[i*4+0], acc[b]);
                            acc[b] = ffma2(h0.y, wreg[i*4+1], acc[b]);
                            acc[b] = ffma2(h1.x, wreg[i*4+2], acc[b]);
                            acc[b] = ffma2(h1.y, wreg[i*4+3], acc[b]);
                        }
                    }
                    #pragma unroll
                    for (int b = 0; b < 8; b++) {
                        float s = hsum2(acc[b]);
                        s += __shfl_xor_sync(0xffffffffu, s, 8);
                        s += __shfl_xor_sync(0xffffffffu, s, 16);
                        if (ks == 0) parts[row*17 + half*8 + b] = s;
                    }
                }
            }
        }
        __syncthreads();
        // phase 2: gate math; h_next via DSMEM to all peer CTAs (double-buffered)
        if (oact) {
            float ghr = br + parts[prI];
            float ghz = bz + parts[pzI];
            float ghn = bn + parts[pnI];
            float rr2 = 1.f/(1.f + expf(-(xr + ghr)));
            float zz = 1.f/(1.f + expf(-(xz + ghz)));
            float nn = tanhf(xn + rr2*ghn);
            float hv = (1.f - zz)*nn + zz*h_s[cur][hpDst];
            if (t + 1 < T) {
                unsigned d = dst0 + (unsigned)nb * (HBUF*4);
                for (int j = 0; j < nrk; j++) st_peer(d, (unsigned)(rkb + j), hv);
            } else {
                hgfin[hoff] = hv;
            }
        }
        CLUSTER_ARRIVE();
        CLUSTER_WAIT();
    }
}

// ---------------- K3: position dense ----------------------------------------
__global__ void __launch_bounds__(256) posdense_k(
    const float* __restrict__ posW, const float* __restrict__ posb,
    const float* __restrict__ ptab) {
    __shared__ float in_s[24*260];
    int c0 = blockIdx.x * 32;
    int tid = threadIdx.x;
    for (int i = tid; i < 24*260; i += 256) {
        int d = i / 260, k = i - d*260;
        in_s[i] = (k < 256) ? g_hc[d*256 + k] : ptab[(d % 12)*4 + (k - 256)];
    }
    __syncthreads();
    int kg = tid & 7, cx = tid >> 3;
    int c = c0 + cx;
    int k0 = kg*33, k1 = (kg == 7) ? 260 : k0 + 33;
    float acc[24];
    #pragma unroll
    for (int d = 0; d < 24; d++) acc[d] = 0.f;
    const float* wr = posW + (size_t)c*260;
    for (int k = k0; k < k1; k++) {
        float wv = wr[k];
        #pragma unroll
        for (int d = 0; d < 24; d++) acc[d] = fmaf(wv, in_s[d*260 + k], acc[d]);
    }
    #pragma unroll
    for (int d = 0; d < 24; d++) {
        float s = acc[d];
        s += __shfl_xor_sync(0xffffffffu, s, 1);
        s += __shfl_xor_sync(0xffffffffu, s, 2);
        s += __shfl_xor_sync(0xffffffffu, s, 4);
        if (kg == 0) g_cfin[d*256 + c] = s + posb[c];
    }
}

// ---------------- K4: attention memory read -> g_qpn -------------------------
__global__ void __launch_bounds__(256) attend_k() {
    __shared__ float enc[256];
    __shared__ float wgt[24];
    int q = blockIdx.x, tid = threadIdx.x;
    enc[tid] = g_hq[q*256 + tid];
    __syncthreads();
    if (tid < 192) {
        int d = tid >> 3, sg = tid & 7;
        const float4* ar = (const float4*)(g_ha + d*256 + sg*32);
        const float4* er = (const float4*)(enc + sg*32);
        float s = 0.f;
        #pragma unroll
        for (int i = 0; i < 8; i++) s = dot4(er[i], ar[i], s);
        s += __shfl_xor_sync(0xffffffffu, s, 1);
        s += __shfl_xor_sync(0xffffffffu, s, 2);
        s += __shfl_xor_sync(0xffffffffu, s, 4);
        if (sg == 0) wgt[d] = s;
    }
    __syncthreads();
    if (tid < 2) {
        int off = tid*12;
        float mx = -1e30f;
        for (int d = 0; d < 12; d++) mx = fmaxf(mx, wgt[off+d]);
        float sum = 0.f;
        for (int d = 0; d < 12; d++) { float e = expf(wgt[off+d]-mx); wgt[off+d]=e; sum += e; }
        float inv = 1.f/sum;
        for (int d = 0; d < 12; d++) wgt[off+d] *= inv;
    }
    __syncthreads();
    float v = enc[tid];
    #pragma unroll
    for (int d = 0; d < 24; d++) v = fmaf(wgt[d], g_cfin[d*256 + tid], v);
    g_qpn[q*256 + tid] = v;
}

// ---------------- K5: final GEMM + gate fused, W read once -------------------
__global__ void __launch_bounds__(256) gemmgate_k(
    const float* __restrict__ qWih, const float* __restrict__ qbih,
    const float* __restrict__ qbhh, float* __restrict__ out) {
    __shared__ float res[24*66];
    int c0 = blockIdx.x * 8;
    int tid = threadIdx.x;
    int w = tid >> 5, lane = tid & 31;
    int q = (w & 1)*32 + lane;
    int rg = w >> 1;

    u64 acc[6];
    #pragma unroll
    for (int j = 0; j < 6; j++) acc[j] = 0ull;

    const float* qrow = g_qpn + (size_t)q*HID;
    #pragma unroll
    for (int ck = 0; ck < 8; ck++) {
        int k0 = ck*32;
        u64 qv[16];
        #pragma unroll
        for (int i = 0; i < 4; i++) {
            ulonglong2 p = *(const ulonglong2*)(qrow + k0 + i*8);
            ulonglong2 p2 = *(const ulonglong2*)(qrow + k0 + i*8 + 4);
            qv[i*4+0]=p.x; qv[i*4+1]=p.y; qv[i*4+2]=p2.x; qv[i*4+3]=p2.y;
        }
        #pragma unroll
        for (int j = 0; j < 6; j++) {
            int rowIdx = rg*6 + j;
            int gate = rowIdx >> 3, col = rowIdx & 7;
            const float* wr = qWih + (size_t)(gate*256 + c0 + col)*HID + k0;
            #pragma unroll
            for (int i = 0; i < 4; i++) {
                ulonglong2 p = *(const ulonglong2*)(wr + i*8);
                ulonglong2 p2 = *(const ulonglong2*)(wr + i*8 + 4);
                acc[j] = ffma2(qv[i*4+0], p.x, acc[j]);
                acc[j] = ffma2(qv[i*4+1], p.y, acc[j]);
                acc[j] = ffma2(qv[i*4+2], p2.x, acc[j]);
                acc[j] = ffma2(qv[i*4+3], p2.y, acc[j]);
            }
        }
    }
    #pragma unroll
    for (int j = 0; j < 6; j++)
        res[(rg*6 + j)*66 + q] = hsum2(acc[j]);
    __syncthreads();

    for (int o = tid; o < 512; o += 256) {
        int oq = o >> 3, col = o & 7;
        int c = c0 + col;
        float gr = res[(col)*66 + oq]      + qbih[c];
        float gz = res[(8+col)*66 + oq]    + qbih[256+c];
        float gn = res[(16+col)*66 + oq]   + qbih[512+c];
        float rv = 1.f/(1.f + expf(-(gr + qbhh[c])));
        float zv = 1.f/(1.f + expf(-(gz + qbhh[256+c])));
        float nv = tanhf(gn + rv*qbhh[512+c]);
        out[oq*256 + c] = (1.f - zv)*nv;
    }
}

// ---------------- launch ------------------------------------------------------
extern "C" void kernel_launch(void* const* d_in, const int* in_sizes, int n_in,
                              void* d_out, int out_size) {
    const int*   qt   = (const int*)d_in[0];
    const int*   pt   = (const int*)d_in[1];
    const int*   nt   = (const int*)d_in[2];
    const float* temb = (const float*)d_in[3];
    const float* tWih = (const float*)d_in[4];
    const float* tWhh = (const float*)d_in[5];
    const float* tbih = (const float*)d_in[6];
    const float* tbhh = (const float*)d_in[7];
    const float* demb = (const float*)d_in[8];
    const float* cWih = (const float*)d_in[9];
    const float* cWhh = (const float*)d_in[10];
    const float* cbih = (const float*)d_in[11];
    const float* cbhh = (const float*)d_in[12];
    const float* aWih = (const float*)d_in[13];
    const float* aWhh = (const float*)d_in[14];
    const float* abih = (const float*)d_in[15];
    const float* abhh = (const float*)d_in[16];
    const float* ptab = (const float*)d_in[17];
    const float* posW = (const float*)d_in[18];
    const float* posb = (const float*)d_in[19];
    const float* qWih = (const float*)d_in[20];
    const float* qbih = (const float*)d_in[22];
    const float* qbhh = (const float*)d_in[23];

    gi_gemm_k<<<120, 256>>>(qt, pt, nt, temb, demb,
                            tWih, tbih, cWih, cbih, aWih, abih);

    // scan with clusters of 16 (non-portable size)
    cudaFuncSetAttribute(scan_k, cudaFuncAttributeNonPortableClusterSizeAllowed, 1);
    cudaLaunchConfig_t cfg = {};
    cfg.gridDim = dim3(128, 1, 1);
    cfg.blockDim = dim3(512, 1, 1);
    cfg.dynamicSmemBytes = 0;
    cudaLaunchAttribute attrs[1];
    attrs[0].id = cudaLaunchAttributeClusterDimension;
    attrs[0].val.clusterDim.x = 16;
    attrs[0].val.clusterDim.y = 1;
    attrs[0].val.clusterDim.z = 1;
    cfg.attrs = attrs;
    cfg.numAttrs = 1;
    cudaLaunchKernelEx(&cfg, scan_k, tWhh, tbhh, cWhh, cbhh, aWhh, abhh);

    posdense_k<<<8, 256>>>(posW, posb, ptab);
    attend_k<<<QN, 256>>>();
    gemmgate_k<<<32, 256>>>(qWih, qbih, qbhh, (float*)d_out);
}

// round 8
// speedup vs baseline: 1.2851x; 1.2851x over previous
#include <cuda_runtime.h>
#include <math.h>

#define HID 256
#define QN 64
#define LQ 20
#define DN 24
#define LD 50
#define QROWS (QN*LQ)   // 1280
#define DROWS (DN*LD)   // 1200

typedef unsigned long long u64;

__device__ __forceinline__ u64 ffma2(u64 a, u64 b, u64 c) {
    u64 d; asm("fma.rn.f32x2 %0, %1, %2, %3;" : "=l"(d) : "l"(a), "l"(b), "l"(c)); return d;
}
__device__ __forceinline__ float hsum2(u64 s) {
    float lo, hi; asm("mov.b64 {%0, %1}, %2;" : "=f"(lo), "=f"(hi) : "l"(s)); return lo + hi;
}
__device__ __forceinline__ void unpack2(u64 s, float& lo, float& hi) {
    asm("mov.b64 {%0, %1}, %2;" : "=f"(lo), "=f"(hi) : "l"(s));
}
__device__ __forceinline__ u64 dupf(float v) {
    u64 d; asm("mov.b64 %0, {%1, %1};" : "=l"(d) : "f"(v)); return d;
}
__device__ __forceinline__ float dot4(float4 a, float4 b, float s) {
    s = fmaf(a.x, b.x, s); s = fmaf(a.y, b.y, s);
    s = fmaf(a.z, b.z, s); s = fmaf(a.w, b.w, s);
    return s;
}
// fast sigmoid / tanh via MUFU.EX2 (rel err ~2^-21 for ex2; fdividef ~rcp.approx)
__device__ __forceinline__ float sigf(float x) {
    return __fdividef(1.f, 1.f + __expf(-x));
}
__device__ __forceinline__ float tanhfast(float x) {
    // tanh(x) = 1 - 2/(exp(2x)+1)
    return 1.f - __fdividef(2.f, __expf(2.f*x) + 1.f);
}

// ---------------- scratch ----------------------------------------------------
__device__ __align__(16) float g_giq[QROWS*768];
__device__ __align__(16) float g_gic[DROWS*768];
__device__ __align__(16) float g_gia[DROWS*768];
__device__ __align__(16) float g_hq[2][QN*HID];
__device__ __align__(16) float g_hc[2][DN*HID];
__device__ __align__(16) float g_ha[2][DN*HID];
__device__ __align__(16) float g_cfin[DN*HID];
__device__ __align__(16) float g_qpn[QN*HID];
__device__ __align__(16) unsigned g_bar[512];

// ---------------- K1: gi = emb[tok] @ W^T + b, gather fused, f32x2 -----------
#define GBM 128
#define GBN 192
#define GBK 32
#define ASD 132
#define BSD 196

__global__ void __launch_bounds__(256) gi_gemm_k(
    const int* __restrict__ qt, const int* __restrict__ pt, const int* __restrict__ nt,
    const float* __restrict__ temb, const float* __restrict__ demb,
    const float* __restrict__ tW, const float* __restrict__ tb,
    const float* __restrict__ cW, const float* __restrict__ cb,
    const float* __restrict__ aW, const float* __restrict__ ab) {
    __shared__ float As[GBK*ASD];
    __shared__ float Bs[GBK*BSD];
    __shared__ int toks[GBM];

    int bid = blockIdx.x;
    int tid = threadIdx.x;
    // zero the scan barriers here (scan_k runs after this kernel in-stream)
    if (bid == 0 && tid < 128)
        ((float4*)g_bar)[tid] = make_float4(0.f,0.f,0.f,0.f);

    int seg = bid / 40;          // 0=query, 1=doc-c, 2=doc-a
    int rem = bid - seg*40;
    int mtl = rem >> 2, ntl = rem & 3;
    int m0 = mtl*GBM, n0 = ntl*GBN;

    const float* W; const float* bias; float* C; const float* emb; int M;
    if (seg == 0)      { W=tW; bias=tb; C=g_giq; emb=temb; M=QROWS; }
    else if (seg == 1) { W=cW; bias=cb; C=g_gic; emb=demb; M=DROWS; }
    else               { W=aW; bias=ab; C=g_gia; emb=demb; M=DROWS; }

    if (tid < GBM) {
        int m = m0 + tid;
        int tk = 0;
        if (m < M) {
            if (seg == 0) tk = qt[m];
            else tk = (m < 600) ? pt[m] : nt[m-600];
        }
        toks[tid] = tk;
    }
    __syncthreads();

    int tx = tid & 15, ty = tid >> 4;
    u64 acc2[4][12];
    #pragma unroll
    for (int p = 0; p < 4; p++)
        #pragma unroll
        for (int j = 0; j < 12; j++) acc2[p][j] = 0ull;

    for (int k0 = 0; k0 < HID; k0 += GBK) {
        #pragma unroll
        for (int q = 0; q < 4; q++) {
            int idx = q*256 + tid;
            int kq = idx >> 7, m = idx & 127;
            float4 v = make_float4(0.f,0.f,0.f,0.f);
            if (m0 + m < M) v = *(const float4*)(emb + (size_t)toks[m]*HID + k0 + kq*4);
            As[(kq*4+0)*ASD + m] = v.x; As[(kq*4+1)*ASD + m] = v.y;
            As[(kq*4+2)*ASD + m] = v.z; As[(kq*4+3)*ASD + m] = v.w;
        }
        #pragma unroll
        for (int q = 0; q < 6; q++) {
            int idx = q*256 + tid;
            int kq = idx / 192, n = idx - kq*192;
            float4 v = *(const float4*)(W + (size_t)(n0+n)*HID + k0 + kq*4);
            Bs[(kq*4+0)*BSD + n] = v.x; Bs[(kq*4+1)*BSD + n] = v.y;
            Bs[(kq*4+2)*BSD + n] = v.z; Bs[(kq*4+3)*BSD + n] = v.w;
        }
        __syncthreads();
        #pragma unroll 8
        for (int k = 0; k < GBK; k++) {
            ulonglong2 A01 = *(const ulonglong2*)(As + k*ASD + ty*8);
            ulonglong2 A23 = *(const ulonglong2*)(As + k*ASD + ty*8 + 4);
            u64 a2[4] = {A01.x, A01.y, A23.x, A23.y};
            float4 b0 = *(const float4*)(Bs + k*BSD + tx*4);
            float4 b1 = *(const float4*)(Bs + k*BSD + 64 + tx*4);
            float4 b2 = *(const float4*)(Bs + k*BSD + 128 + tx*4);
            u64 bb[12];
            bb[0]=dupf(b0.x); bb[1]=dupf(b0.y); bb[2]=dupf(b0.z); bb[3]=dupf(b0.w);
            bb[4]=dupf(b1.x); bb[5]=dupf(b1.y); bb[6]=dupf(b1.z); bb[7]=dupf(b1.w);
            bb[8]=dupf(b2.x); bb[9]=dupf(b2.y); bb[10]=dupf(b2.z); bb[11]=dupf(b2.w);
            #pragma unroll
            for (int p = 0; p < 4; p++)
                #pragma unroll
                for (int j = 0; j < 12; j++)
                    acc2[p][j] = ffma2(a2[p], bb[j], acc2[p][j]);
        }
        __syncthreads();
    }

    float4 bv[3];
    #pragma unroll
    for (int g = 0; g < 3; g++)
        bv[g] = *(const float4*)(bias + n0 + g*64 + tx*4);
    #pragma unroll
    for (int p = 0; p < 4; p++) {
        float vlo[12], vhi[12];
        #pragma unroll
        for (int j = 0; j < 12; j++) unpack2(acc2[p][j], vlo[j], vhi[j]);
        #pragma unroll
        for (int e = 0; e < 2; e++) {
            int m = m0 + ty*8 + p*2 + e;
            if (m >= M) continue;
            const float* vv = e ? vhi : vlo;
            #pragma unroll
            for (int g = 0; g < 3; g++) {
                float4 o;
                o.x = vv[g*4+0] + (&bv[g].x)[0];
                o.y = vv[g*4+1] + (&bv[g].x)[1];
                o.z = vv[g*4+2] + (&bv[g].x)[2];
                o.w = vv[g*4+3] + (&bv[g].x)[3];
                *(float4*)(C + (size_t)m*768 + n0 + g*64 + tx*4) = o;
            }
        }
    }
}

// ---------------- K2: GRU scans, f32x2, W in regs, k-split 4 -----------------
__device__ __forceinline__ void bar_arrive_wait(unsigned* p, unsigned need) {
    asm volatile("red.release.gpu.global.add.u32 [%0], %1;" :: "l"(p), "r"(1u) : "memory");
    unsigned v;
    do {
        asm volatile("ld.acquire.gpu.global.u32 %0, [%1];" : "=r"(v) : "l"(p) : "memory");
    } while (v < need);
}

__global__ void __launch_bounds__(512) scan_k(
    const float* __restrict__ tWhh, const float* __restrict__ tbhh,
    const float* __restrict__ cWhh, const float* __restrict__ cbhh,
    const float* __restrict__ aWhh, const float* __restrict__ abhh) {
    __shared__ float h_s[16*256];
    __shared__ float parts[96*17];

    int bid = blockIdx.x, tid = threadIdx.x;
    bool isQ = (bid >= 96);
    int lane = tid & 31;
    int r = lane & 7, ks = lane >> 3;
    int row = (tid >> 5)*8 + r;
    bool act = tid < 384;

    int bg, c0, T, PB;
    unsigned* bar; unsigned need;
    if (!isQ) { bg = bid >> 4; c0 = (bid & 15) << 4; T = LD; PB = 5;  bar = g_bar + bg*64;        need = 16; }
    else { int qg = bid - 96; bg = qg >> 3; c0 = (qg & 7) << 5; T = LQ; PB = 17; bar = g_bar + 384 + bg*32; need = 8; }

    u64 wreg[32];
    int hrow0 = 0;
    if (act) {
        const float* Wp; int grow;
        if (!isQ) {
            int chain = row / 48, rr = row - (row/48)*48;
            grow = (rr >> 4)*256 + c0 + (rr & 15);
            Wp = chain ? aWhh : cWhh;
            hrow0 = chain * 4;
        } else {
            grow = (row >> 5)*256 + c0 + (row & 31);
            Wp = tWhh;
        }
        const float* base = Wp + (size_t)grow*HID + ks*64;
        #pragma unroll
        for (int i = 0; i < 8; i++) {
            int ch = (i + ks) & 7;
            ulonglong2 p0 = *(const ulonglong2*)(base + ch*8);
            ulonglong2 p1 = *(const ulonglong2*)(base + ch*8 + 4);
            wreg[i*4+0]=p0.x; wreg[i*4+1]=p0.y; wreg[i*4+2]=p1.x; wreg[i*4+3]=p1.y;
        }
    }

    bool oact; int prI=0, pzI=0, pnI=0, hpI=0, hoff=0, cc=0;
    float br=0.f, bz=0.f, bn=0.f;
    const float* giBase = nullptr;
    int docChain = 0;
    if (!isQ) {
        oact = (tid < 128);
        if (oact) {
            int chain = tid >> 6, b = (tid >> 4) & 3, cl = tid & 15;
            docChain = chain;
            cc = c0 + cl;
            prI = (chain*48 + cl)*PB + b; pzI = prI + 16*PB; pnI = prI + 32*PB;
            hpI = (chain*4 + b)*256 + cc;
            const float* bh = chain ? abhh : cbhh;
            br = bh[cc]; bz = bh[256+cc]; bn = bh[512+cc];
            giBase = (chain ? g_gia : g_gic) + (size_t)(bg*4 + b)*LD*768;
            hoff = (bg*4 + b)*256 + cc;
        }
    } else {
        oact = true;
        int b = tid >> 5, cl = tid & 31;
        cc = c0 + cl;
        prI = cl*PB + b; pzI = (32+cl)*PB + b; pnI = (64+cl)*PB + b;
        hpI = b*256 + cc;
        br = tbhh[cc]; bz = tbhh[256+cc]; bn = tbhh[512+cc];
        giBase = g_giq + (size_t)(bg*16 + b)*LQ*768;
        hoff = (bg*16 + b)*256 + cc;
    }

    #pragma unroll
    for (int i = 0; i < 2; i++)
        ((float4*)h_s)[tid + i*512] = make_float4(0.f,0.f,0.f,0.f);
    __syncthreads();

    for (int t = 0; t < T; t++) {
        float xr=0.f, xz=0.f, xn=0.f;
        if (oact) {
            const float* gp = giBase + (size_t)t*768;
            xr = gp[cc]; xz = gp[256+cc]; xn = gp[512+cc];
        }
        if (act) {
            if (!isQ) {
                u64 acc[4];
                #pragma unroll
                for (int b = 0; b < 4; b++) acc[b] = 0ull;
                #pragma unroll
                for (int i = 0; i < 8; i++) {
                    int off = ((i + ks) & 7) * 8 + ks*64;
                    #pragma unroll
                    for (int b = 0; b < 4; b++) {
                        const float* hp = h_s + (hrow0 + b)*256 + off;
                        ulonglong2 h0 = *(const ulonglong2*)hp;
                        ulonglong2 h1 = *(const ulonglong2*)(hp + 4);
                        acc[b] = ffma2(h0.x, wreg[i*4+0], acc[b]);
                        acc[b] = ffma2(h0.y, wreg[i*4+1], acc[b]);
                        acc[b] = ffma2(h1.x, wreg[i*4+2], acc[b]);
                        acc[b] = ffma2(h1.y, wreg[i*4+3], acc[b]);
                    }
                }
                #pragma unroll
                for (int b = 0; b < 4; b++) {
                    float s = hsum2(acc[b]);
                    s += __shfl_xor_sync(0xffffffffu, s, 8);
                    s += __shfl_xor_sync(0xffffffffu, s, 16);
                    if (ks == 0) parts[row*5 + b] = s;
                }
            } else {
                #pragma unroll
                for (int half = 0; half < 2; half++) {
                    u64 acc[8];
                    #pragma unroll
                    for (int b = 0; b < 8; b++) acc[b] = 0ull;
                    #pragma unroll
                    for (int i = 0; i < 8; i++) {
                        int off = ((i + ks) & 7) * 8 + ks*64;
                        #pragma unroll
                        for (int b = 0; b < 8; b++) {
                            const float* hp = h_s + (half*8 + b)*256 + off;
                            ulonglong2 h0 = *(const ulonglong2*)hp;
                            ulonglong2 h1 = *(const ulonglong2*)(hp + 4);
                            acc[b] = ffma2(h0.x, wreg[i*4+0], acc[b]);
                            acc[b] = ffma2(h0.y, wreg[i*4+1], acc[b]);
                            acc[b] = ffma2(h1.x, wreg[i*4+2], acc[b]);
                            acc[b] = ffma2(h1.y, wreg[i*4+3], acc[b]);
                        }
                    }
                    #pragma unroll
                    for (int b = 0; b < 8; b++) {
                        float s = hsum2(acc[b]);
                        s += __shfl_xor_sync(0xffffffffu, s, 8);
                        s += __shfl_xor_sync(0xffffffffu, s, 16);
                        if (ks == 0) parts[row*17 + half*8 + b] = s;
                    }
                }
            }
        }
        __syncthreads();
        int nb = (t+1) & 1;
        if (oact) {
            float ghr = br + parts[prI];
            float ghz = bz + parts[pzI];
            float ghn = bn + parts[pnI];
            float rr2 = sigf(xr + ghr);
            float zz = sigf(xz + ghz);
            float nn = tanhfast(xn + rr2*ghn);
            float hv = (1.f - zz)*nn + zz*h_s[hpI];
            float* hdst;
            if (!isQ) hdst = docChain ? g_ha[nb] : g_hc[nb];
            else      hdst = g_hq[nb];
            hdst[hoff] = hv;
        }
        __syncthreads();
        if (tid == 0) bar_arrive_wait(bar + t, need);
        __syncthreads();
        if (t+1 < T) {
            if (!isQ) {
                int rw = tid >> 6, col = tid & 63;
                int chain = rw >> 2, b = rw & 3;
                const float* src = (chain ? g_ha[nb] : g_hc[nb]) + (size_t)(bg*4 + b)*256;
                ((float4*)h_s)[rw*64 + col] = __ldcg((const float4*)src + col);
            } else {
                #pragma unroll
                for (int i = 0; i < 2; i++) {
                    int idx = tid + i*512;
                    int rw = idx >> 6, col = idx & 63;
                    const float* src = g_hq[nb] + (size_t)(bg*16 + rw)*256;
                    ((float4*)h_s)[rw*64 + col] = __ldcg((const float4*)src + col);
                }
            }
            __syncthreads();
        }
    }
}

// ---------------- K3: position dense ----------------------------------------
__global__ void __launch_bounds__(256) posdense_k(
    const float* __restrict__ posW, const float* __restrict__ posb,
    const float* __restrict__ ptab) {
    __shared__ float in_s[24*260];
    int c0 = blockIdx.x * 32;
    int tid = threadIdx.x;
    for (int i = tid; i < 24*260; i += 256) {
        int d = i / 260, k = i - d*260;
        in_s[i] = (k < 256) ? g_hc[0][d*256 + k] : ptab[(d % 12)*4 + (k - 256)];
    }
    __syncthreads();
    int kg = tid & 7, cx = tid >> 3;
    int c = c0 + cx;
    int k0 = kg*33, k1 = (kg == 7) ? 260 : k0 + 33;
    float acc[24];
    #pragma unroll
    for (int d = 0; d < 24; d++) acc[d] = 0.f;
    const float* wr = posW + (size_t)c*260;
    for (int k = k0; k < k1; k++) {
        float wv = wr[k];
        #pragma unroll
        for (int d = 0; d < 24; d++) acc[d] = fmaf(wv, in_s[d*260 + k], acc[d]);
    }
    #pragma unroll
    for (int d = 0; d < 24; d++) {
        float s = acc[d];
        s += __shfl_xor_sync(0xffffffffu, s, 1);
        s += __shfl_xor_sync(0xffffffffu, s, 2);
        s += __shfl_xor_sync(0xffffffffu, s, 4);
        if (kg == 0) g_cfin[d*256 + c] = s + posb[c];
    }
}

// ---------------- K4: attention memory read -> g_qpn -------------------------
__global__ void __launch_bounds__(256) attend_k() {
    __shared__ float enc[256];
    __shared__ float wgt[24];
    int q = blockIdx.x, tid = threadIdx.x;
    enc[tid] = g_hq[0][q*256 + tid];
    __syncthreads();
    if (tid < 192) {
        int d = tid >> 3, sg = tid & 7;
        const float4* ar = (const float4*)(g_ha[0] + d*256 + sg*32);
        const float4* er = (const float4*)(enc + sg*32);
        float s = 0.f;
        #pragma unroll
        for (int i = 0; i < 8; i++) s = dot4(er[i], ar[i], s);
        s += __shfl_xor_sync(0xffffffffu, s, 1);
        s += __shfl_xor_sync(0xffffffffu, s, 2);
        s += __shfl_xor_sync(0xffffffffu, s, 4);
        if (sg == 0) wgt[d] = s;
    }
    __syncthreads();
    if (tid < 2) {
        int off = tid*12;
        float mx = -1e30f;
        for (int d = 0; d < 12; d++) mx = fmaxf(mx, wgt[off+d]);
        float sum = 0.f;
        for (int d = 0; d < 12; d++) { float e = __expf(wgt[off+d]-mx); wgt[off+d]=e; sum += e; }
        float inv = __fdividef(1.f, sum);
        for (int d = 0; d < 12; d++) wgt[off+d] *= inv;
    }
    __syncthreads();
    float v = enc[tid];
    #pragma unroll
    for (int d = 0; d < 24; d++) v = fmaf(wgt[d], g_cfin[d*256 + tid], v);
    g_qpn[q*256 + tid] = v;
}

// ---------------- K5: final GEMM + gate fused, W read once -------------------
__global__ void __launch_bounds__(256) gemmgate_k(
    const float* __restrict__ qWih, const float* __restrict__ qbih,
    const float* __restrict__ qbhh, float* __restrict__ out) {
    __shared__ float res[24*66];
    int c0 = blockIdx.x * 8;
    int tid = threadIdx.x;
    int w = tid >> 5, lane = tid & 31;
    int q = (w & 1)*32 + lane;
    int rg = w >> 1;

    u64 acc[6];
    #pragma unroll
    for (int j = 0; j < 6; j++) acc[j] = 0ull;

    const float* qrow = g_qpn + (size_t)q*HID;
    #pragma unroll
    for (int ck = 0; ck < 8; ck++) {
        int k0 = ck*32;
        u64 qv[16];
        #pragma unroll
        for (int i = 0; i < 4; i++) {
            ulonglong2 p = *(const ulonglong2*)(qrow + k0 + i*8);
            ulonglong2 p2 = *(const ulonglong2*)(qrow + k0 + i*8 + 4);
            qv[i*4+0]=p.x; qv[i*4+1]=p.y; qv[i*4+2]=p2.x; qv[i*4+3]=p2.y;
        }
        #pragma unroll
        for (int j = 0; j < 6; j++) {
            int rowIdx = rg*6 + j;
            int gate = rowIdx >> 3, col = rowIdx & 7;
            const float* wr = qWih + (size_t)(gate*256 + c0 + col)*HID + k0;
            #pragma unroll
            for (int i = 0; i < 4; i++) {
                ulonglong2 p = *(const ulonglong2*)(wr + i*8);
                ulonglong2 p2 = *(const ulonglong2*)(wr + i*8 + 4);
                acc[j] = ffma2(qv[i*4+0], p.x, acc[j]);
                acc[j] = ffma2(qv[i*4+1], p.y, acc[j]);
                acc[j] = ffma2(qv[i*4+2], p2.x, acc[j]);
                acc[j] = ffma2(qv[i*4+3], p2.y, acc[j]);
            }
        }
    }
    #pragma unroll
    for (int j = 0; j < 6; j++)
        res[(rg*6 + j)*66 + q] = hsum2(acc[j]);
    __syncthreads();

    for (int o = tid; o < 512; o += 256) {
        int oq = o >> 3, col = o & 7;
        int c = c0 + col;
        float gr = res[(col)*66 + oq]      + qbih[c];
        float gz = res[(8+col)*66 + oq]    + qbih[256+c];
        float gn = res[(16+col)*66 + oq]   + qbih[512+c];
        float rv = sigf(gr + qbhh[c]);
        float zv = sigf(gz + qbhh[256+c]);
        float nv = tanhfast(gn + rv*qbhh[512+c]);
        out[oq*256 + c] = (1.f - zv)*nv;
    }
}

// ---------------- launch ------------------------------------------------------
extern "C" void kernel_launch(void* const* d_in, const int* in_sizes, int n_in,
                              void* d_out, int out_size) {
    const int*   qt   = (const int*)d_in[0];
    const int*   pt   = (const int*)d_in[1];
    const int*   nt   = (const int*)d_in[2];
    const float* temb = (const float*)d_in[3];
    const float* tWih = (const float*)d_in[4];
    const float* tWhh = (const float*)d_in[5];
    const float* tbih = (const float*)d_in[6];
    const float* tbhh = (const float*)d_in[7];
    const float* demb = (const float*)d_in[8];
    const float* cWih = (const float*)d_in[9];
    const float* cWhh = (const float*)d_in[10];
    const float* cbih = (const float*)d_in[11];
    const float* cbhh = (const float*)d_in[12];
    const float* aWih = (const float*)d_in[13];
    const float* aWhh = (const float*)d_in[14];
    const float* abih = (const float*)d_in[15];
    const float* abhh = (const float*)d_in[16];
    const float* ptab = (const float*)d_in[17];
    const float* posW = (const float*)d_in[18];
    const float* posb = (const float*)d_in[19];
    const float* qWih = (const float*)d_in[20];
    const float* qbih = (const float*)d_in[22];
    const float* qbhh = (const float*)d_in[23];

    gi_gemm_k<<<120, 256>>>(qt, pt, nt, temb, demb,
                            tWih, tbih, cWih, cbih, aWih, abih);
    scan_k<<<128, 512>>>(tWhh, tbhh, cWhh, cbhh, aWhh, abhh);
    posdense_k<<<8, 256>>>(posW, posb, ptab);
    attend_k<<<QN, 256>>>();
    gemmgate_k<<<32, 256>>>(qWih, qbih, qbhh, (float*)d_out);
}

// round 9
// speedup vs baseline: 1.3441x; 1.0459x over previous
#include <cuda_runtime.h>
#include <math.h>

#define HID 256
#define QN 64
#define LQ 20
#define DN 24
#define LD 50
#define QROWS (QN*LQ)   // 1280
#define DROWS (DN*LD)   // 1200

typedef unsigned long long u64;

__device__ __forceinline__ u64 ffma2(u64 a, u64 b, u64 c) {
    u64 d; asm("fma.rn.f32x2 %0, %1, %2, %3;" : "=l"(d) : "l"(a), "l"(b), "l"(c)); return d;
}
__device__ __forceinline__ float hsum2(u64 s) {
    float lo, hi; asm("mov.b64 {%0, %1}, %2;" : "=f"(lo), "=f"(hi) : "l"(s)); return lo + hi;
}
__device__ __forceinline__ void unpack2(u64 s, float& lo, float& hi) {
    asm("mov.b64 {%0, %1}, %2;" : "=f"(lo), "=f"(hi) : "l"(s));
}
__device__ __forceinline__ u64 dupf(float v) {
    u64 d; asm("mov.b64 %0, {%1, %1};" : "=l"(d) : "f"(v)); return d;
}
__device__ __forceinline__ float dot4(float4 a, float4 b, float s) {
    s = fmaf(a.x, b.x, s); s = fmaf(a.y, b.y, s);
    s = fmaf(a.z, b.z, s); s = fmaf(a.w, b.w, s);
    return s;
}
__device__ __forceinline__ float sigf(float x) {
    return __fdividef(1.f, 1.f + __expf(-x));
}
__device__ __forceinline__ float tanhfast(float x) {
    return 1.f - __fdividef(2.f, __expf(2.f*x) + 1.f);
}

// ---------------- scratch ----------------------------------------------------
__device__ __align__(16) float g_giq[QROWS*768];
__device__ __align__(16) float g_gic[DROWS*768];
__device__ __align__(16) float g_gia[DROWS*768];
__device__ __align__(16) float g_hq[2][QN*HID];
__device__ __align__(16) float g_hc[2][DN*HID];
__device__ __align__(16) float g_ha[2][DN*HID];
__device__ __align__(16) float g_cfin[DN*HID];
__device__ __align__(16) float g_qpn[QN*HID];
__device__ __align__(16) unsigned g_bar[512];

// ---------------- K1: gi = emb[tok] @ W^T + b, gather fused, f32x2 -----------
#define GBM 128
#define GBN 192
#define GBK 32
#define ASD 132
#define BSD 196

__global__ void __launch_bounds__(256) gi_gemm_k(
    const int* __restrict__ qt, const int* __restrict__ pt, const int* __restrict__ nt,
    const float* __restrict__ temb, const float* __restrict__ demb,
    const float* __restrict__ tW, const float* __restrict__ tb,
    const float* __restrict__ cW, const float* __restrict__ cb,
    const float* __restrict__ aW, const float* __restrict__ ab) {
    __shared__ float As[GBK*ASD];
    __shared__ float Bs[GBK*BSD];
    __shared__ int toks[GBM];

    int bid = blockIdx.x;
    int tid = threadIdx.x;
    // zero all scan barrier counters (scan_k runs after this kernel in-stream)
    if (bid == 0 && tid < 128)
        ((float4*)g_bar)[tid] = make_float4(0.f,0.f,0.f,0.f);

    int seg = bid / 40;          // 0=query, 1=doc-c, 2=doc-a
    int rem = bid - seg*40;
    int mtl = rem >> 2, ntl = rem & 3;
    int m0 = mtl*GBM, n0 = ntl*GBN;

    const float* W; const float* bias; float* C; const float* emb; int M;
    if (seg == 0)      { W=tW; bias=tb; C=g_giq; emb=temb; M=QROWS; }
    else if (seg == 1) { W=cW; bias=cb; C=g_gic; emb=demb; M=DROWS; }
    else               { W=aW; bias=ab; C=g_gia; emb=demb; M=DROWS; }

    if (tid < GBM) {
        int m = m0 + tid;
        int tk = 0;
        if (m < M) {
            if (seg == 0) tk = qt[m];
            else tk = (m < 600) ? pt[m] : nt[m-600];
        }
        toks[tid] = tk;
    }
    __syncthreads();

    int tx = tid & 15, ty = tid >> 4;
    u64 acc2[4][12];
    #pragma unroll
    for (int p = 0; p < 4; p++)
        #pragma unroll
        for (int j = 0; j < 12; j++) acc2[p][j] = 0ull;

    for (int k0 = 0; k0 < HID; k0 += GBK) {
        #pragma unroll
        for (int q = 0; q < 4; q++) {
            int idx = q*256 + tid;
            int kq = idx >> 7, m = idx & 127;
            float4 v = make_float4(0.f,0.f,0.f,0.f);
            if (m0 + m < M) v = *(const float4*)(emb + (size_t)toks[m]*HID + k0 + kq*4);
            As[(kq*4+0)*ASD + m] = v.x; As[(kq*4+1)*ASD + m] = v.y;
            As[(kq*4+2)*ASD + m] = v.z; As[(kq*4+3)*ASD + m] = v.w;
        }
        #pragma unroll
        for (int q = 0; q < 6; q++) {
            int idx = q*256 + tid;
            int kq = idx / 192, n = idx - kq*192;
            float4 v = *(const float4*)(W + (size_t)(n0+n)*HID + k0 + kq*4);
            Bs[(kq*4+0)*BSD + n] = v.x; Bs[(kq*4+1)*BSD + n] = v.y;
            Bs[(kq*4+2)*BSD + n] = v.z; Bs[(kq*4+3)*BSD + n] = v.w;
        }
        __syncthreads();
        #pragma unroll 8
        for (int k = 0; k < GBK; k++) {
            ulonglong2 A01 = *(const ulonglong2*)(As + k*ASD + ty*8);
            ulonglong2 A23 = *(const ulonglong2*)(As + k*ASD + ty*8 + 4);
            u64 a2[4] = {A01.x, A01.y, A23.x, A23.y};
            float4 b0 = *(const float4*)(Bs + k*BSD + tx*4);
            float4 b1 = *(const float4*)(Bs + k*BSD + 64 + tx*4);
            float4 b2 = *(const float4*)(Bs + k*BSD + 128 + tx*4);
            u64 bb[12];
            bb[0]=dupf(b0.x); bb[1]=dupf(b0.y); bb[2]=dupf(b0.z); bb[3]=dupf(b0.w);
            bb[4]=dupf(b1.x); bb[5]=dupf(b1.y); bb[6]=dupf(b1.z); bb[7]=dupf(b1.w);
            bb[8]=dupf(b2.x); bb[9]=dupf(b2.y); bb[10]=dupf(b2.z); bb[11]=dupf(b2.w);
            #pragma unroll
            for (int p = 0; p < 4; p++)
                #pragma unroll
                for (int j = 0; j < 12; j++)
                    acc2[p][j] = ffma2(a2[p], bb[j], acc2[p][j]);
        }
        __syncthreads();
    }

    float4 bv[3];
    #pragma unroll
    for (int g = 0; g < 3; g++)
        bv[g] = *(const float4*)(bias + n0 + g*64 + tx*4);
    #pragma unroll
    for (int p = 0; p < 4; p++) {
        float vlo[12], vhi[12];
        #pragma unroll
        for (int j = 0; j < 12; j++) unpack2(acc2[p][j], vlo[j], vhi[j]);
        #pragma unroll
        for (int e = 0; e < 2; e++) {
            int m = m0 + ty*8 + p*2 + e;
            if (m >= M) continue;
            const float* vv = e ? vhi : vlo;
            #pragma unroll
            for (int g = 0; g < 3; g++) {
                float4 o;
                o.x = vv[g*4+0] + (&bv[g].x)[0];
                o.y = vv[g*4+1] + (&bv[g].x)[1];
                o.z = vv[g*4+2] + (&bv[g].x)[2];
                o.w = vv[g*4+3] + (&bv[g].x)[3];
                *(float4*)(C + (size_t)m*768 + n0 + g*64 + tx*4) = o;
            }
        }
    }
}

// ---------------- K2: GRU scans + fused tail ---------------------------------
__device__ __forceinline__ void bar_arrive_wait(unsigned* p, unsigned need) {
    asm volatile("red.release.gpu.global.add.u32 [%0], %1;" :: "l"(p), "r"(1u) : "memory");
    unsigned v;
    do {
        asm volatile("ld.acquire.gpu.global.u32 %0, [%1];" : "=r"(v) : "l"(p) : "memory");
    } while (v < need);
}

__global__ void __launch_bounds__(512) scan_k(
    const float* __restrict__ tWhh, const float* __restrict__ tbhh,
    const float* __restrict__ cWhh, const float* __restrict__ cbhh,
    const float* __restrict__ aWhh, const float* __restrict__ abhh,
    const float* __restrict__ ptab, const float* __restrict__ posW,
    const float* __restrict__ posb,
    const float* __restrict__ qWih, const float* __restrict__ qbih,
    const float* __restrict__ qbhh, float* __restrict__ out) {
    __shared__ __align__(16) float pool[6240];   // h_s(4096) + parts(1632) | in_s(6240) | res(1584)
    float* h_s = pool;
    float* parts = pool + 4096;

    int bid = blockIdx.x, tid = threadIdx.x;
    bool isQ = (bid >= 96);
    int lane = tid & 31;
    int r = lane & 7, ks = lane >> 3;
    int row = (tid >> 5)*8 + r;
    bool act = tid < 384;

    int bg, c0, T, PB;
    unsigned* bar; unsigned need;
    if (!isQ) { bg = bid >> 4; c0 = (bid & 15) << 4; T = LD; PB = 5;  bar = g_bar + bg*64;        need = 16; }
    else { int qg = bid - 96; bg = qg >> 3; c0 = (qg & 7) << 5; T = LQ; PB = 17; bar = g_bar + 384 + bg*32; need = 8; }

    u64 wreg[32];
    int hrow0 = 0;
    if (act) {
        const float* Wp; int grow;
        if (!isQ) {
            int chain = row / 48, rr = row - (row/48)*48;
            grow = (rr >> 4)*256 + c0 + (rr & 15);
            Wp = chain ? aWhh : cWhh;
            hrow0 = chain * 4;
        } else {
            grow = (row >> 5)*256 + c0 + (row & 31);
            Wp = tWhh;
        }
        const float* base = Wp + (size_t)grow*HID + ks*64;
        #pragma unroll
        for (int i = 0; i < 8; i++) {
            int ch = (i + ks) & 7;
            ulonglong2 p0 = *(const ulonglong2*)(base + ch*8);
            ulonglong2 p1 = *(const ulonglong2*)(base + ch*8 + 4);
            wreg[i*4+0]=p0.x; wreg[i*4+1]=p0.y; wreg[i*4+2]=p1.x; wreg[i*4+3]=p1.y;
        }
    }

    bool oact; int prI=0, pzI=0, pnI=0, hpI=0, hoff=0, cc=0;
    float br=0.f, bz=0.f, bn=0.f;
    const float* giBase = nullptr;
    int docChain = 0;
    if (!isQ) {
        oact = (tid < 128);
        if (oact) {
            int chain = tid >> 6, b = (tid >> 4) & 3, cl = tid & 15;
            docChain = chain;
            cc = c0 + cl;
            prI = (chain*48 + cl)*PB + b; pzI = prI + 16*PB; pnI = prI + 32*PB;
            hpI = (chain*4 + b)*256 + cc;
            const float* bh = chain ? abhh : cbhh;
            br = bh[cc]; bz = bh[256+cc]; bn = bh[512+cc];
            giBase = (chain ? g_gia : g_gic) + (size_t)(bg*4 + b)*LD*768;
            hoff = (bg*4 + b)*256 + cc;
        }
    } else {
        oact = true;
        int b = tid >> 5, cl = tid & 31;
        cc = c0 + cl;
        prI = cl*PB + b; pzI = (32+cl)*PB + b; pnI = (64+cl)*PB + b;
        hpI = b*256 + cc;
        br = tbhh[cc]; bz = tbhh[256+cc]; bn = tbhh[512+cc];
        giBase = g_giq + (size_t)(bg*16 + b)*LQ*768;
        hoff = (bg*16 + b)*256 + cc;
    }

    #pragma unroll
    for (int i = 0; i < 2; i++)
        ((float4*)h_s)[tid + i*512] = make_float4(0.f,0.f,0.f,0.f);
    __syncthreads();

    for (int t = 0; t < T; t++) {
        float xr=0.f, xz=0.f, xn=0.f;
        if (oact) {
            const float* gp = giBase + (size_t)t*768;
            xr = gp[cc]; xz = gp[256+cc]; xn = gp[512+cc];
        }
        if (act) {
            if (!isQ) {
                u64 acc[4];
                #pragma unroll
                for (int b = 0; b < 4; b++) acc[b] = 0ull;
                #pragma unroll
                for (int i = 0; i < 8; i++) {
                    int off = ((i + ks) & 7) * 8 + ks*64;
                    #pragma unroll
                    for (int b = 0; b < 4; b++) {
                        const float* hp = h_s + (hrow0 + b)*256 + off;
                        ulonglong2 h0 = *(const ulonglong2*)hp;
                        ulonglong2 h1 = *(const ulonglong2*)(hp + 4);
                        acc[b] = ffma2(h0.x, wreg[i*4+0], acc[b]);
                        acc[b] = ffma2(h0.y, wreg[i*4+1], acc[b]);
                        acc[b] = ffma2(h1.x, wreg[i*4+2], acc[b]);
                        acc[b] = ffma2(h1.y, wreg[i*4+3], acc[b]);
                    }
                }
                #pragma unroll
                for (int b = 0; b < 4; b++) {
                    float s = hsum2(acc[b]);
                    s += __shfl_xor_sync(0xffffffffu, s, 8);
                    s += __shfl_xor_sync(0xffffffffu, s, 16);
                    if (ks == 0) parts[row*5 + b] = s;
                }
            } else {
                #pragma unroll
                for (int half = 0; half < 2; half++) {
                    u64 acc[8];
                    #pragma unroll
                    for (int b = 0; b < 8; b++) acc[b] = 0ull;
                    #pragma unroll
                    for (int i = 0; i < 8; i++) {
                        int off = ((i + ks) & 7) * 8 + ks*64;
                        #pragma unroll
                        for (int b = 0; b < 8; b++) {
                            const float* hp = h_s + (half*8 + b)*256 + off;
                            ulonglong2 h0 = *(const ulonglong2*)hp;
                            ulonglong2 h1 = *(const ulonglong2*)(hp + 4);
                            acc[b] = ffma2(h0.x, wreg[i*4+0], acc[b]);
                            acc[b] = ffma2(h0.y, wreg[i*4+1], acc[b]);
                            acc[b] = ffma2(h1.x, wreg[i*4+2], acc[b]);
                            acc[b] = ffma2(h1.y, wreg[i*4+3], acc[b]);
                        }
                    }
                    #pragma unroll
                    for (int b = 0; b < 8; b++) {
                        float s = hsum2(acc[b]);
                        s += __shfl_xor_sync(0xffffffffu, s, 8);
                        s += __shfl_xor_sync(0xffffffffu, s, 16);
                        if (ks == 0) parts[row*17 + half*8 + b] = s;
                    }
                }
            }
        }
        __syncthreads();
        int nb = (t+1) & 1;
        if (oact) {
            float ghr = br + parts[prI];
            float ghz = bz + parts[pzI];
            float ghn = bn + parts[pnI];
            float rr2 = sigf(xr + ghr);
            float zz = sigf(xz + ghz);
            float nn = tanhfast(xn + rr2*ghn);
            float hv = (1.f - zz)*nn + zz*h_s[hpI];
            float* hdst;
            if (!isQ) hdst = docChain ? g_ha[nb] : g_hc[nb];
            else      hdst = g_hq[nb];
            hdst[hoff] = hv;
        }
        __syncthreads();
        if (tid == 0) bar_arrive_wait(bar + t, need);
        __syncthreads();
        if (t+1 < T) {
            if (!isQ) {
                int rw = tid >> 6, col = tid & 63;
                int chain = rw >> 2, b = rw & 3;
                const float* src = (chain ? g_ha[nb] : g_hc[nb]) + (size_t)(bg*4 + b)*256;
                ((float4*)h_s)[rw*64 + col] = __ldcg((const float4*)src + col);
            } else {
                #pragma unroll
                for (int i = 0; i < 2; i++) {
                    int idx = tid + i*512;
                    int rw = idx >> 6, col = idx & 63;
                    const float* src = g_hq[nb] + (size_t)(bg*16 + rw)*256;
                    ((float4*)h_s)[rw*64 + col] = __ldcg((const float4*)src + col);
                }
            }
            __syncthreads();
        }
    }

    // ================= fused tail =================
    // final h states live in g_hc[0], g_ha[0], g_hq[0]
    __syncthreads();
    if (tid == 0) bar_arrive_wait(g_bar + 500, 128);
    __syncthreads();

    // ---- T1: posdense (CTAs 0-7) | attention scores+softmax (CTAs 8-71) ----
    if (bid < 8) {
        float* in_s = pool;
        int c0p = bid * 32;
        for (int i = tid; i < 24*260; i += 512) {
            int d = i / 260, k = i - d*260;
            in_s[i] = (k < 256) ? g_hc[0][d*256 + k] : ptab[(d % 12)*4 + (k - 256)];
        }
        __syncthreads();
        if (tid < 256) {
            int kg = tid & 7, cx = tid >> 3;
            int c = c0p + cx;
            int k0 = kg*33, k1 = (kg == 7) ? 260 : k0 + 33;
            float accp[24];
            #pragma unroll
            for (int d = 0; d < 24; d++) accp[d] = 0.f;
            const float* wr = posW + (size_t)c*260;
            for (int k = k0; k < k1; k++) {
                float wv = wr[k];
                #pragma unroll
                for (int d = 0; d < 24; d++) accp[d] = fmaf(wv, in_s[d*260 + k], accp[d]);
            }
            #pragma unroll
            for (int d = 0; d < 24; d++) {
                float s = accp[d];
                s += __shfl_xor_sync(0xffffffffu, s, 1);
                s += __shfl_xor_sync(0xffffffffu, s, 2);
                s += __shfl_xor_sync(0xffffffffu, s, 4);
                if (kg == 0) g_cfin[d*256 + c] = s + posb[c];
            }
        }
    } else if (bid < 72) {
        int q = bid - 8;
        float* enc = pool;          // 256
        float* wgt = pool + 256;    // 24
        if (tid < 256) enc[tid] = g_hq[0][q*256 + tid];
        __syncthreads();
        if (tid < 192) {
            int d = tid >> 3, sg = tid & 7;
            const float4* ar = (const float4*)(g_ha[0] + d*256 + sg*32);
            const float4* er = (const float4*)(enc + sg*32);
            float s = 0.f;
            #pragma unroll
            for (int i = 0; i < 8; i++) s = dot4(er[i], ar[i], s);
            s += __shfl_xor_sync(0xffffffffu, s, 1);
            s += __shfl_xor_sync(0xffffffffu, s, 2);
            s += __shfl_xor_sync(0xffffffffu, s, 4);
            if (sg == 0) wgt[d] = s;
        }
        __syncthreads();
        if (tid < 2) {
            int off = tid*12;
            float mx = -1e30f;
            for (int d = 0; d < 12; d++) mx = fmaxf(mx, wgt[off+d]);
            float sum = 0.f;
            for (int d = 0; d < 12; d++) { float e = __expf(wgt[off+d]-mx); wgt[off+d]=e; sum += e; }
            float inv = __fdividef(1.f, sum);
            for (int d = 0; d < 12; d++) wgt[off+d] *= inv;
        }
    }
    __syncthreads();
    if (tid == 0) bar_arrive_wait(g_bar + 501, 128);
    __syncthreads();

    // ---- T2: qpn = enc + sum w*cfin (CTAs 8-71; enc/wgt still in smem) ----
    if (bid >= 8 && bid < 72 && tid < 256) {
        int q = bid - 8;
        float* enc = pool;
        float* wgt = pool + 256;
        float v = enc[tid];
        #pragma unroll
        for (int d = 0; d < 24; d++) v = fmaf(wgt[d], g_cfin[d*256 + tid], v);
        g_qpn[q*256 + tid] = v;
    }
    __syncthreads();
    if (tid == 0) bar_arrive_wait(g_bar + 502, 128);
    __syncthreads();

    // ---- T3: final GEMM + gate (CTAs 0-31) ----
    if (bid < 32) {
        float* res = pool;          // 24*66 = 1584
        int c0g = bid * 8;
        if (tid < 256) {
            int w = tid >> 5, ln = tid & 31;
            int q = (w & 1)*32 + ln;
            int rg = w >> 1;
            u64 acc[6];
            #pragma unroll
            for (int j = 0; j < 6; j++) acc[j] = 0ull;
            const float* qrow = g_qpn + (size_t)q*HID;
            #pragma unroll
            for (int ck = 0; ck < 8; ck++) {
                int k0 = ck*32;
                u64 qv[16];
                #pragma unroll
                for (int i = 0; i < 4; i++) {
                    ulonglong2 p = *(const ulonglong2*)(qrow + k0 + i*8);
                    ulonglong2 p2 = *(const ulonglong2*)(qrow + k0 + i*8 + 4);
                    qv[i*4+0]=p.x; qv[i*4+1]=p.y; qv[i*4+2]=p2.x; qv[i*4+3]=p2.y;
                }
                #pragma unroll
                for (int j = 0; j < 6; j++) {
                    int rowIdx = rg*6 + j;
                    int gate = rowIdx >> 3, col = rowIdx & 7;
                    const float* wr = qWih + (size_t)(gate*256 + c0g + col)*HID + k0;
                    #pragma unroll
                    for (int i = 0; i < 4; i++) {
                        ulonglong2 p = *(const ulonglong2*)(wr + i*8);
                        ulonglong2 p2 = *(const ulonglong2*)(wr + i*8 + 4);
                        acc[j] = ffma2(qv[i*4+0], p.x, acc[j]);
                        acc[j] = ffma2(qv[i*4+1], p.y, acc[j]);
                        acc[j] = ffma2(qv[i*4+2], p2.x, acc[j]);
                        acc[j] = ffma2(qv[i*4+3], p2.y, acc[j]);
                    }
                }
            }
            #pragma unroll
            for (int j = 0; j < 6; j++)
                res[(rg*6 + j)*66 + q] = hsum2(acc[j]);
        }
        __syncthreads();
        if (tid < 256) {
            for (int o = tid; o < 512; o += 256) {
                int oq = o >> 3, col = o & 7;
                int c = c0g + col;
                float gr = res[(col)*66 + oq]      + qbih[c];
                float gz = res[(8+col)*66 + oq]    + qbih[256+c];
                float gn = res[(16+col)*66 + oq]   + qbih[512+c];
                float rv = sigf(gr + qbhh[c]);
                float zv = sigf(gz + qbhh[256+c]);
                float nv = tanhfast(gn + rv*qbhh[512+c]);
                out[oq*256 + c] = (1.f - zv)*nv;
            }
        }
    }
}

// ---------------- launch ------------------------------------------------------
extern "C" void kernel_launch(void* const* d_in, const int* in_sizes, int n_in,
                              void* d_out, int out_size) {
    const int*   qt   = (const int*)d_in[0];
    const int*   pt   = (const int*)d_in[1];
    const int*   nt   = (const int*)d_in[2];
    const float* temb = (const float*)d_in[3];
    const float* tWih = (const float*)d_in[4];
    const float* tWhh = (const float*)d_in[5];
    const float* tbih = (const float*)d_in[6];
    const float* tbhh = (const float*)d_in[7];
    const float* demb = (const float*)d_in[8];
    const float* cWih = (const float*)d_in[9];
    const float* cWhh = (const float*)d_in[10];
    const float* cbih = (const float*)d_in[11];
    const float* cbhh = (const float*)d_in[12];
    const float* aWih = (const float*)d_in[13];
    const float* aWhh = (const float*)d_in[14];
    const float* abih = (const float*)d_in[15];
    const float* abhh = (const float*)d_in[16];
    const float* ptab = (const float*)d_in[17];
    const float* posW = (const float*)d_in[18];
    const float* posb = (const float*)d_in[19];
    const float* qWih = (const float*)d_in[20];
    const float* qbih = (const float*)d_in[22];
    const float* qbhh = (const float*)d_in[23];

    gi_gemm_k<<<120, 256>>>(qt, pt, nt, temb, demb,
                            tWih, tbih, cWih, cbih, aWih, abih);
    scan_k<<<128, 512>>>(tWhh, tbhh, cWhh, cbhh, aWhh, abhh,
                         ptab, posW, posb, qWih, qbih, qbhh, (float*)d_out);
}

// round 10
// speedup vs baseline: 1.4026x; 1.0435x over previous
#include <cuda_runtime.h>
#include <math.h>

#define HID 256
#define QN 64
#define LQ 20
#define DN 24
#define LD 50
#define QROWS (QN*LQ)   // 1280
#define DROWS (DN*LD)   // 1200

typedef unsigned long long u64;

__device__ __forceinline__ u64 ffma2(u64 a, u64 b, u64 c) {
    u64 d; asm("fma.rn.f32x2 %0, %1, %2, %3;" : "=l"(d) : "l"(a), "l"(b), "l"(c)); return d;
}
__device__ __forceinline__ float hsum2(u64 s) {
    float lo, hi; asm("mov.b64 {%0, %1}, %2;" : "=f"(lo), "=f"(hi) : "l"(s)); return lo + hi;
}
__device__ __forceinline__ void unpack2(u64 s, float& lo, float& hi) {
    asm("mov.b64 {%0, %1}, %2;" : "=f"(lo), "=f"(hi) : "l"(s));
}
__device__ __forceinline__ u64 dupf(float v) {
    u64 d; asm("mov.b64 %0, {%1, %1};" : "=l"(d) : "f"(v)); return d;
}
__device__ __forceinline__ float dot4(float4 a, float4 b, float s) {
    s = fmaf(a.x, b.x, s); s = fmaf(a.y, b.y, s);
    s = fmaf(a.z, b.z, s); s = fmaf(a.w, b.w, s);
    return s;
}
__device__ __forceinline__ float sigf(float x) {
    return __fdividef(1.f, 1.f + __expf(-x));
}
__device__ __forceinline__ float tanhfast(float x) {
    return 1.f - __fdividef(2.f, __expf(2.f*x) + 1.f);
}
// atomic 8-byte tagged-pair exchange (value, step-tag)
__device__ __forceinline__ float2 ldp(const float2* p) {
    u64 r; asm volatile("ld.relaxed.gpu.global.b64 %0, [%1];" : "=l"(r) : "l"(p));
    float2 v; asm("mov.b64 {%0, %1}, %2;" : "=f"(v.x), "=f"(v.y) : "l"(r));
    return v;
}
__device__ __forceinline__ void stp(float2* p, float x, float y) {
    u64 r; asm("mov.b64 %0, {%1, %2};" : "=l"(r) : "f"(x), "f"(y));
    asm volatile("st.relaxed.gpu.global.b64 [%0], %1;" :: "l"(p), "l"(r));
}

// ---------------- scratch ----------------------------------------------------
__device__ __align__(16) float g_giq[QROWS*768];
__device__ __align__(16) float g_gic[DROWS*768];
__device__ __align__(16) float g_gia[DROWS*768];
__device__ __align__(16) float2 g_xd[2][48][256];   // doc h exchange (value, tag)
__device__ __align__(16) float2 g_xq[2][64][256];   // query h exchange
__device__ __align__(16) float g_hcf[DN*HID];
__device__ __align__(16) float g_haf[DN*HID];
__device__ __align__(16) float g_hqf[QN*HID];
__device__ __align__(16) float g_cfin[DN*HID];
__device__ __align__(16) float g_qpn[QN*HID];
__device__ __align__(16) unsigned g_bar[512];

// ---------------- K1: gi = emb[tok] @ W^T + b, gather fused, f32x2 -----------
#define GBM 128
#define GBN 192
#define GBK 32
#define ASD 132
#define BSD 196

__global__ void __launch_bounds__(256) gi_gemm_k(
    const int* __restrict__ qt, const int* __restrict__ pt, const int* __restrict__ nt,
    const float* __restrict__ temb, const float* __restrict__ demb,
    const float* __restrict__ tW, const float* __restrict__ tb,
    const float* __restrict__ cW, const float* __restrict__ cb,
    const float* __restrict__ aW, const float* __restrict__ ab) {
    __shared__ float As[GBK*ASD];
    __shared__ float Bs[GBK*BSD];
    __shared__ int toks[GBM];

    int bid = blockIdx.x;
    int tid = threadIdx.x;
    // reset exchange buffers (tag=0, value=0 == h0) and tail barriers each replay
    {
        int gz = bid*256 + tid;
        if (gz < 12288)       ((float4*)g_xd)[gz] = make_float4(0.f,0.f,0.f,0.f);
        else if (gz < 28672)  ((float4*)g_xq)[gz - 12288] = make_float4(0.f,0.f,0.f,0.f);
        if (bid == 0 && tid < 128)
            ((float4*)g_bar)[tid] = make_float4(0.f,0.f,0.f,0.f);
    }

    int seg = bid / 40;          // 0=query, 1=doc-c, 2=doc-a
    int rem = bid - seg*40;
    int mtl = rem >> 2, ntl = rem & 3;
    int m0 = mtl*GBM, n0 = ntl*GBN;

    const float* W; const float* bias; float* C; const float* emb; int M;
    if (seg == 0)      { W=tW; bias=tb; C=g_giq; emb=temb; M=QROWS; }
    else if (seg == 1) { W=cW; bias=cb; C=g_gic; emb=demb; M=DROWS; }
    else               { W=aW; bias=ab; C=g_gia; emb=demb; M=DROWS; }

    if (tid < GBM) {
        int m = m0 + tid;
        int tk = 0;
        if (m < M) {
            if (seg == 0) tk = qt[m];
            else tk = (m < 600) ? pt[m] : nt[m-600];
        }
        toks[tid] = tk;
    }
    __syncthreads();

    int tx = tid & 15, ty = tid >> 4;
    u64 acc2[4][12];
    #pragma unroll
    for (int p = 0; p < 4; p++)
        #pragma unroll
        for (int j = 0; j < 12; j++) acc2[p][j] = 0ull;

    for (int k0 = 0; k0 < HID; k0 += GBK) {
        #pragma unroll
        for (int q = 0; q < 4; q++) {
            int idx = q*256 + tid;
            int kq = idx >> 7, m = idx & 127;
            float4 v = make_float4(0.f,0.f,0.f,0.f);
            if (m0 + m < M) v = *(const float4*)(emb + (size_t)toks[m]*HID + k0 + kq*4);
            As[(kq*4+0)*ASD + m] = v.x; As[(kq*4+1)*ASD + m] = v.y;
            As[(kq*4+2)*ASD + m] = v.z; As[(kq*4+3)*ASD + m] = v.w;
        }
        #pragma unroll
        for (int q = 0; q < 6; q++) {
            int idx = q*256 + tid;
            int kq = idx / 192, n = idx - kq*192;
            float4 v = *(const float4*)(W + (size_t)(n0+n)*HID + k0 + kq*4);
            Bs[(kq*4+0)*BSD + n] = v.x; Bs[(kq*4+1)*BSD + n] = v.y;
            Bs[(kq*4+2)*BSD + n] = v.z; Bs[(kq*4+3)*BSD + n] = v.w;
        }
        __syncthreads();
        #pragma unroll 8
        for (int k = 0; k < GBK; k++) {
            ulonglong2 A01 = *(const ulonglong2*)(As + k*ASD + ty*8);
            ulonglong2 A23 = *(const ulonglong2*)(As + k*ASD + ty*8 + 4);
            u64 a2[4] = {A01.x, A01.y, A23.x, A23.y};
            float4 b0 = *(const float4*)(Bs + k*BSD + tx*4);
            float4 b1 = *(const float4*)(Bs + k*BSD + 64 + tx*4);
            float4 b2 = *(const float4*)(Bs + k*BSD + 128 + tx*4);
            u64 bb[12];
            bb[0]=dupf(b0.x); bb[1]=dupf(b0.y); bb[2]=dupf(b0.z); bb[3]=dupf(b0.w);
            bb[4]=dupf(b1.x); bb[5]=dupf(b1.y); bb[6]=dupf(b1.z); bb[7]=dupf(b1.w);
            bb[8]=dupf(b2.x); bb[9]=dupf(b2.y); bb[10]=dupf(b2.z); bb[11]=dupf(b2.w);
            #pragma unroll
            for (int p = 0; p < 4; p++)
                #pragma unroll
                for (int j = 0; j < 12; j++)
                    acc2[p][j] = ffma2(a2[p], bb[j], acc2[p][j]);
        }
        __syncthreads();
    }

    float4 bv[3];
    #pragma unroll
    for (int g = 0; g < 3; g++)
        bv[g] = *(const float4*)(bias + n0 + g*64 + tx*4);
    #pragma unroll
    for (int p = 0; p < 4; p++) {
        float vlo[12], vhi[12];
        #pragma unroll
        for (int j = 0; j < 12; j++) unpack2(acc2[p][j], vlo[j], vhi[j]);
        #pragma unroll
        for (int e = 0; e < 2; e++) {
            int m = m0 + ty*8 + p*2 + e;
            if (m >= M) continue;
            const float* vv = e ? vhi : vlo;
            #pragma unroll
            for (int g = 0; g < 3; g++) {
                float4 o;
                o.x = vv[g*4+0] + (&bv[g].x)[0];
                o.y = vv[g*4+1] + (&bv[g].x)[1];
                o.z = vv[g*4+2] + (&bv[g].x)[2];
                o.w = vv[g*4+3] + (&bv[g].x)[3];
                *(float4*)(C + (size_t)m*768 + n0 + g*64 + tx*4) = o;
            }
        }
    }
}

// ---------------- K2: GRU scans (tagged-pair exchange) + fused tail ----------
__device__ __forceinline__ void bar_arrive_wait(unsigned* p, unsigned need) {
    asm volatile("red.release.gpu.global.add.u32 [%0], %1;" :: "l"(p), "r"(1u) : "memory");
    unsigned v;
    do {
        asm volatile("ld.acquire.gpu.global.u32 %0, [%1];" : "=r"(v) : "l"(p) : "memory");
    } while (v < need);
}

__global__ void __launch_bounds__(512) scan_k(
    const float* __restrict__ tWhh, const float* __restrict__ tbhh,
    const float* __restrict__ cWhh, const float* __restrict__ cbhh,
    const float* __restrict__ aWhh, const float* __restrict__ abhh,
    const float* __restrict__ ptab, const float* __restrict__ posW,
    const float* __restrict__ posb,
    const float* __restrict__ qWih, const float* __restrict__ qbih,
    const float* __restrict__ qbhh, float* __restrict__ out) {
    __shared__ __align__(16) float pool[9824];   // h_s[2] (2x4096) + parts(1632); tail reuses
    float* parts = pool + 8192;

    int bid = blockIdx.x, tid = threadIdx.x;
    bool isQ = (bid >= 96);
    int lane = tid & 31;
    int r = lane & 7, ks = lane >> 3;
    int row = (tid >> 5)*8 + r;
    bool act = tid < 384;

    int bg, c0, T, PB;
    if (!isQ) { bg = bid >> 4; c0 = (bid & 15) << 4; T = LD; PB = 5; }
    else { int qg = bid - 96; bg = qg >> 3; c0 = (qg & 7) << 5; T = LQ; PB = 17; }

    // ---- W slice into registers (rotated chunks, conflict-free h LDS) -------
    u64 wreg[32];
    int hrow0 = 0;
    if (act) {
        const float* Wp; int grow;
        if (!isQ) {
            int chain = row / 48, rr = row - (row/48)*48;
            grow = (rr >> 4)*256 + c0 + (rr & 15);
            Wp = chain ? aWhh : cWhh;
            hrow0 = chain * 4;
        } else {
            grow = (row >> 5)*256 + c0 + (row & 31);
            Wp = tWhh;
        }
        const float* base = Wp + (size_t)grow*HID + ks*64;
        #pragma unroll
        for (int i = 0; i < 8; i++) {
            int ch = (i + ks) & 7;
            ulonglong2 p0 = *(const ulonglong2*)(base + ch*8);
            ulonglong2 p1 = *(const ulonglong2*)(base + ch*8 + 4);
            wreg[i*4+0]=p0.x; wreg[i*4+1]=p0.y; wreg[i*4+2]=p1.x; wreg[i*4+3]=p1.y;
        }
    }

    // ---- phase-2 (producer) setup -------------------------------------------
    bool oact; int prI=0, pzI=0, pnI=0, hpI=0, hoff=0, cc=0, prow=0;
    float br=0.f, bz=0.f, bn=0.f;
    const float* giBase = nullptr;
    int docChain = 0;
    if (!isQ) {
        oact = (tid < 128);
        if (oact) {
            int chain = tid >> 6, b = (tid >> 4) & 3, cl = tid & 15;
            docChain = chain;
            cc = c0 + cl;
            prI = (chain*48 + cl)*PB + b; pzI = prI + 16*PB; pnI = prI + 32*PB;
            hpI = (chain*4 + b)*256 + cc;
            const float* bh = chain ? abhh : cbhh;
            br = bh[cc]; bz = bh[256+cc]; bn = bh[512+cc];
            giBase = (chain ? g_gia : g_gic) + (size_t)(bg*4 + b)*LD*768;
            hoff = (bg*4 + b)*256 + cc;
            prow = chain*24 + bg*4 + b;
        }
    } else {
        oact = true;
        int b = tid >> 5, cl = tid & 31;
        cc = c0 + cl;
        prI = cl*PB + b; pzI = (32+cl)*PB + b; pnI = (64+cl)*PB + b;
        hpI = b*256 + cc;
        br = tbhh[cc]; bz = tbhh[256+cc]; bn = tbhh[512+cc];
        giBase = g_giq + (size_t)(bg*16 + b)*LQ*768;
        hoff = (bg*16 + b)*256 + cc;
        prow = bg*16 + b;
    }

    // ---- staging (consumer) setup -------------------------------------------
    int srow, scol, sdst;
    if (!isQ) {
        int p0 = tid*4;
        int lrow = p0 >> 8; scol = p0 & 255;
        int chain = lrow >> 2, bb = lrow & 3;
        srow = chain*24 + bg*4 + bb;
        sdst = lrow*256 + scol;
    } else {
        int p0 = tid*8;
        int lrow = p0 >> 8; scol = p0 & 255;
        srow = bg*16 + lrow;
        sdst = lrow*256 + scol;
    }

    for (int t = 0; t < T; t++) {
        int cur = t & 1;
        float* hs = pool + cur*4096;
        // prefetch this step's gi (independent of h)
        float xr=0.f, xz=0.f, xn=0.f;
        if (oact) {
            const float* gp = giBase + (size_t)t*768;
            xr = gp[cc]; xz = gp[256+cc]; xn = gp[512+cc];
        }
        // ---- stage h(t): poll tagged pairs, copy into smem ----
        float tgt = (float)t;
        if (!isQ) {
            const float2* sp = &g_xd[cur][srow][scol];
            float2 v0, v1, v2, v3;
            do {
                v0 = ldp(sp);   v1 = ldp(sp+1);
                v2 = ldp(sp+2); v3 = ldp(sp+3);
            } while (v0.y != tgt || v1.y != tgt || v2.y != tgt || v3.y != tgt);
            *(float4*)(hs + sdst) = make_float4(v0.x, v1.x, v2.x, v3.x);
        } else {
            const float2* sp = &g_xq[cur][srow][scol];
            float2 v[8]; bool ok;
            do {
                #pragma unroll
                for (int i = 0; i < 8; i++) v[i] = ldp(sp + i);
                ok = true;
                #pragma unroll
                for (int i = 0; i < 8; i++) ok &= (v[i].y == tgt);
            } while (!ok);
            *(float4*)(hs + sdst)     = make_float4(v[0].x, v[1].x, v[2].x, v[3].x);
            *(float4*)(hs + sdst + 4) = make_float4(v[4].x, v[5].x, v[6].x, v[7].x);
        }
        __syncthreads();
        // ---- phase 1: gh partials, W in regs, h from smem ----
        if (act) {
            if (!isQ) {
                u64 acc[4];
                #pragma unroll
                for (int b = 0; b < 4; b++) acc[b] = 0ull;
                #pragma unroll
                for (int i = 0; i < 8; i++) {
                    int off = ((i + ks) & 7) * 8 + ks*64;
                    #pragma unroll
                    for (int b = 0; b < 4; b++) {
                        const float* hp = hs + (hrow0 + b)*256 + off;
                        ulonglong2 h0 = *(const ulonglong2*)hp;
                        ulonglong2 h1 = *(const ulonglong2*)(hp + 4);
                        acc[b] = ffma2(h0.x, wreg[i*4+0], acc[b]);
                        acc[b] = ffma2(h0.y, wreg[i*4+1], acc[b]);
                        acc[b] = ffma2(h1.x, wreg[i*4+2], acc[b]);
                        acc[b] = ffma2(h1.y, wreg[i*4+3], acc[b]);
                    }
                }
                #pragma unroll
                for (int b = 0; b < 4; b++) {
                    float s = hsum2(acc[b]);
                    s += __shfl_xor_sync(0xffffffffu, s, 8);
                    s += __shfl_xor_sync(0xffffffffu, s, 16);
                    if (ks == 0) parts[row*5 + b] = s;
                }
            } else {
                #pragma unroll
                for (int half = 0; half < 2; half++) {
                    u64 acc[8];
                    #pragma unroll
                    for (int b = 0; b < 8; b++) acc[b] = 0ull;
                    #pragma unroll
                    for (int i = 0; i < 8; i++) {
                        int off = ((i + ks) & 7) * 8 + ks*64;
                        #pragma unroll
                        for (int b = 0; b < 8; b++) {
                            const float* hp = hs + (half*8 + b)*256 + off;
                            ulonglong2 h0 = *(const ulonglong2*)hp;
                            ulonglong2 h1 = *(const ulonglong2*)(hp + 4);
                            acc[b] = ffma2(h0.x, wreg[i*4+0], acc[b]);
                            acc[b] = ffma2(h0.y, wreg[i*4+1], acc[b]);
                            acc[b] = ffma2(h1.x, wreg[i*4+2], acc[b]);
                            acc[b] = ffma2(h1.y, wreg[i*4+3], acc[b]);
                        }
                    }
                    #pragma unroll
                    for (int b = 0; b < 8; b++) {
                        float s = hsum2(acc[b]);
                        s += __shfl_xor_sync(0xffffffffu, s, 8);
                        s += __shfl_xor_sync(0xffffffffu, s, 16);
                        if (ks == 0) parts[row*17 + half*8 + b] = s;
                    }
                }
            }
        }
        __syncthreads();
        // ---- phase 2: gate math, publish h(t+1) as tagged pair ----
        if (oact) {
            float ghr = br + parts[prI];
            float ghz = bz + parts[pzI];
            float ghn = bn + parts[pnI];
            float rr2 = sigf(xr + ghr);
            float zz = sigf(xz + ghz);
            float nn = tanhfast(xn + rr2*ghn);
            float hv = (1.f - zz)*nn + zz*hs[hpI];
            if (t + 1 < T) {
                float2* dp = (!isQ) ? &g_xd[(t+1)&1][prow][cc] : &g_xq[(t+1)&1][prow][cc];
                stp(dp, hv, (float)(t+1));
            } else {
                if (!isQ) (docChain ? g_haf : g_hcf)[hoff] = hv;
                else      g_hqf[hoff] = hv;
            }
        }
        // no barrier: next iteration's poll is the barrier
    }

    // ================= fused tail =================
    __syncthreads();
    if (tid == 0) bar_arrive_wait(g_bar + 500, 128);
    __syncthreads();

    // ---- T1: posdense (CTAs 0-7) | attention scores+softmax (CTAs 8-71) ----
    if (bid < 8) {
        float* in_s = pool;
        int c0p = bid * 32;
        for (int i = tid; i < 24*260; i += 512) {
            int d = i / 260, k = i - d*260;
            in_s[i] = (k < 256) ? g_hcf[d*256 + k] : ptab[(d % 12)*4 + (k - 256)];
        }
        __syncthreads();
        if (tid < 256) {
            int kg = tid & 7, cx = tid >> 3;
            int c = c0p + cx;
            int k0 = kg*33, k1 = (kg == 7) ? 260 : k0 + 33;
            float accp[24];
            #pragma unroll
            for (int d = 0; d < 24; d++) accp[d] = 0.f;
            const float* wr = posW + (size_t)c*260;
            for (int k = k0; k < k1; k++) {
                float wv = wr[k];
                #pragma unroll
                for (int d = 0; d < 24; d++) accp[d] = fmaf(wv, in_s[d*260 + k], accp[d]);
            }
            #pragma unroll
            for (int d = 0; d < 24; d++) {
                float s = accp[d];
                s += __shfl_xor_sync(0xffffffffu, s, 1);
                s += __shfl_xor_sync(0xffffffffu, s, 2);
                s += __shfl_xor_sync(0xffffffffu, s, 4);
                if (kg == 0) g_cfin[d*256 + c] = s + posb[c];
            }
        }
    } else if (bid < 72) {
        int q = bid - 8;
        float* enc = pool;
        float* wgt = pool + 256;
        if (tid < 256) enc[tid] = g_hqf[q*256 + tid];
        __syncthreads();
        if (tid < 192) {
            int d = tid >> 3, sg = tid & 7;
            const float4* ar = (const float4*)(g_haf + d*256 + sg*32);
            const float4* er = (const float4*)(enc + sg*32);
            float s = 0.f;
            #pragma unroll
            for (int i = 0; i < 8; i++) s = dot4(er[i], ar[i], s);
            s += __shfl_xor_sync(0xffffffffu, s, 1);
            s += __shfl_xor_sync(0xffffffffu, s, 2);
            s += __shfl_xor_sync(0xffffffffu, s, 4);
            if (sg == 0) wgt[d] = s;
        }
        __syncthreads();
        if (tid < 2) {
            int off = tid*12;
            float mx = -1e30f;
            for (int d = 0; d < 12; d++) mx = fmaxf(mx, wgt[off+d]);
            float sum = 0.f;
            for (int d = 0; d < 12; d++) { float e = __expf(wgt[off+d]-mx); wgt[off+d]=e; sum += e; }
            float inv = __fdividef(1.f, sum);
            for (int d = 0; d < 12; d++) wgt[off+d] *= inv;
        }
    }
    __syncthreads();
    if (tid == 0) bar_arrive_wait(g_bar + 501, 128);
    __syncthreads();

    // ---- T2: qpn = enc + sum w*cfin (CTAs 8-71) ----
    if (bid >= 8 && bid < 72 && tid < 256) {
        int q = bid - 8;
        float* enc = pool;
        float* wgt = pool + 256;
        float v = enc[tid];
        #pragma unroll
        for (int d = 0; d < 24; d++) v = fmaf(wgt[d], g_cfin[d*256 + tid], v);
        g_qpn[q*256 + tid] = v;
    }
    __syncthreads();
    if (tid == 0) bar_arrive_wait(g_bar + 502, 128);
    __syncthreads();

    // ---- T3: final GEMM + gate (CTAs 0-31) ----
    if (bid < 32) {
        float* res = pool;
        int c0g = bid * 8;
        if (tid < 256) {
            int w = tid >> 5, ln = tid & 31;
            int q = (w & 1)*32 + ln;
            int rg = w >> 1;
            u64 acc[6];
            #pragma unroll
            for (int j = 0; j < 6; j++) acc[j] = 0ull;
            const float* qrow = g_qpn + (size_t)q*HID;
            #pragma unroll
            for (int ck = 0; ck < 8; ck++) {
                int k0 = ck*32;
                u64 qv[16];
                #pragma unroll
                for (int i = 0; i < 4; i++) {
                    ulonglong2 p = *(const ulonglong2*)(qrow + k0 + i*8);
                    ulonglong2 p2 = *(const ulonglong2*)(qrow + k0 + i*8 + 4);
                    qv[i*4+0]=p.x; qv[i*4+1]=p.y; qv[i*4+2]=p2.x; qv[i*4+3]=p2.y;
                }
                #pragma unroll
                for (int j = 0; j < 6; j++) {
                    int rowIdx = rg*6 + j;
                    int gate = rowIdx >> 3, col = rowIdx & 7;
                    const float* wr = qWih + (size_t)(gate*256 + c0g + col)*HID + k0;
                    #pragma unroll
                    for (int i = 0; i < 4; i++) {
                        ulonglong2 p = *(const ulonglong2*)(wr + i*8);
                        ulonglong2 p2 = *(const ulonglong2*)(wr + i*8 + 4);
                        acc[j] = ffma2(qv[i*4+0], p.x, acc[j]);
                        acc[j] = ffma2(qv[i*4+1], p.y, acc[j]);
                        acc[j] = ffma2(qv[i*4+2], p2.x, acc[j]);
                        acc[j] = ffma2(qv[i*4+3], p2.y, acc[j]);
                    }
                }
            }
            #pragma unroll
            for (int j = 0; j < 6; j++)
                res[(rg*6 + j)*66 + q] = hsum2(acc[j]);
        }
        __syncthreads();
        if (tid < 256) {
            for (int o = tid; o < 512; o += 256) {
                int oq = o >> 3, col = o & 7;
                int c = c0g + col;
                float gr = res[(col)*66 + oq]      + qbih[c];
                float gz = res[(8+col)*66 + oq]    + qbih[256+c];
                float gn = res[(16+col)*66 + oq]   + qbih[512+c];
                float rv = sigf(gr + qbhh[c]);
                float zv = sigf(gz + qbhh[256+c]);
                float nv = tanhfast(gn + rv*qbhh[512+c]);
                out[oq*256 + c] = (1.f - zv)*nv;
            }
        }
    }
}

// ---------------- launch ------------------------------------------------------
extern "C" void kernel_launch(void* const* d_in, const int* in_sizes, int n_in,
                              void* d_out, int out_size) {
    const int*   qt   = (const int*)d_in[0];
    const int*   pt   = (const int*)d_in[1];
    const int*   nt   = (const int*)d_in[2];
    const float* temb = (const float*)d_in[3];
    const float* tWih = (const float*)d_in[4];
    const float* tWhh = (const float*)d_in[5];
    const float* tbih = (const float*)d_in[6];
    const float* tbhh = (const float*)d_in[7];
    const float* demb = (const float*)d_in[8];
    const float* cWih = (const float*)d_in[9];
    const float* cWhh = (const float*)d_in[10];
    const float* cbih = (const float*)d_in[11];
    const float* cbhh = (const float*)d_in[12];
    const float* aWih = (const float*)d_in[13];
    const float* aWhh = (const float*)d_in[14];
    const float* abih = (const float*)d_in[15];
    const float* abhh = (const float*)d_in[16];
    const float* ptab = (const float*)d_in[17];
    const float* posW = (const float*)d_in[18];
    const float* posb = (const float*)d_in[19];
    const float* qWih = (const float*)d_in[20];
    const float* qbih = (const float*)d_in[22];
    const float* qbhh = (const float*)d_in[23];

    gi_gemm_k<<<120, 256>>>(qt, pt, nt, temb, demb,
                            tWih, tbih, cWih, cbih, aWih, abih);
    scan_k<<<128, 512>>>(tWhh, tbhh, cWhh, cbhh, aWhh, abhh,
                         ptab, posW, posb, qWih, qbih, qbhh, (float*)d_out);
}